// round 1
// baseline (speedup 1.0000x reference)
#include <cuda_runtime.h>

#define PATCH 41
#define NPIX (PATCH * PATCH)
#define NBINS 128
#define NTHREADS 256

static __device__ __forceinline__ float block_reduce_sum(float v, float* red) {
    // 256-thread full-block sum; result broadcast to all threads.
    #pragma unroll
    for (int o = 16; o > 0; o >>= 1) v += __shfl_xor_sync(0xffffffffu, v, o);
    __syncthreads();                       // protect red[] reuse across calls
    if ((threadIdx.x & 31) == 0) red[threadIdx.x >> 5] = v;
    __syncthreads();
    float s = 0.f;
    #pragma unroll
    for (int w = 0; w < NTHREADS / 32; ++w) s += red[w];
    return s;
}

__global__ void __launch_bounds__(NTHREADS, 8)
sift_desc_kernel(const float* __restrict__ x,
                 const float* __restrict__ gk,
                 float* __restrict__ out) {
    __shared__ float sx[NPIX];
    __shared__ float sgk[NPIX];
    __shared__ float hist[NBINS];
    __shared__ float red[NTHREADS / 32];

    const int p   = blockIdx.x;
    const int tid = threadIdx.x;
    const float* xp = x + (size_t)p * NPIX;

    for (int i = tid; i < NPIX; i += NTHREADS) {
        sx[i]  = xp[i];
        sgk[i] = gk[i];
    }
    if (tid < NBINS) hist[tid] = 0.f;
    __syncthreads();

    const float TWO_PI = 6.28318530717958647692f;
    const float ANG_SCALE = 8.0f / TWO_PI;

    for (int i = tid; i < NPIX; i += NTHREADS) {
        const int r = i / PATCH;
        const int c = i - r * PATCH;

        // replicate-pad central differences
        const float gxv = sx[r * PATCH + (c < PATCH - 1 ? c + 1 : c)]
                        - sx[r * PATCH + (c > 0 ? c - 1 : c)];
        const float gyv = sx[(r < PATCH - 1 ? r + 1 : r) * PATCH + c]
                        - sx[(r > 0 ? r - 1 : r) * PATCH + c];

        const float mag = sqrtf(gxv * gxv + gyv * gyv + 1e-10f) * sgk[i];
        const float ori = atan2f(gyv, gxv + 1e-10f);

        // soft angular binning
        const float f  = (ori + TWO_PI) * ANG_SCALE;   // in (4, 12]
        const float bf = floorf(f);
        const float w1 = f - bf;
        const int b0 = ((int)bf) & 7;
        const int b1 = (b0 + 1) & 7;
        const float m1 = w1 * mag;
        const float m0 = (1.0f - w1) * mag;

        // spatial bins: window i covers d = r+4-10*i in [0,16)
        const int iy_min = (r >= 2) ? (r - 2) / 10 : 0;
        const int iy_max = min((r + 4) / 10, 3);
        const int ix_min = (c >= 2) ? (c - 2) / 10 : 0;
        const int ix_max = min((c + 4) / 10, 3);

        for (int iy = iy_min; iy <= iy_max; ++iy) {
            const float dy = (float)(r + 4 - 10 * iy);
            const float wy = (8.0f - fabsf(dy - 7.5f)) * 0.125f;
            for (int ix = ix_min; ix <= ix_max; ++ix) {
                const float dx = (float)(c + 4 - 10 * ix);
                const float wx = (8.0f - fabsf(dx - 7.5f)) * 0.125f;
                const float w = wy * wx;
                const int base = (iy << 2) + ix;
                atomicAdd(&hist[(b0 << 4) + base], w * m0);
                atomicAdd(&hist[(b1 << 4) + base], w * m1);
            }
        }
    }
    __syncthreads();

    // normalization chain: L2 -> clip(0.2) -> L2 -> L1 -> sqrt
    float v = (tid < NBINS) ? hist[tid] : 0.f;

    const float s1 = block_reduce_sum(v * v, red);
    v = v / fmaxf(sqrtf(s1), 1e-12f);
    v = fminf(fmaxf(v, 0.0f), 0.2f);

    const float s2 = block_reduce_sum(v * v, red);
    v = v / fmaxf(sqrtf(s2), 1e-12f);

    const float s3 = block_reduce_sum(fabsf(v), red);
    v = v / fmaxf(s3, 1e-12f);

    if (tid < NBINS) out[(size_t)p * NBINS + tid] = sqrtf(v + 1e-10f);
}

extern "C" void kernel_launch(void* const* d_in, const int* in_sizes, int n_in,
                              void* d_out, int out_size) {
    const float* x  = (const float*)d_in[0];   // [8192,1,41,41]
    const float* gk = (const float*)d_in[1];   // [41,41]
    // d_in[2] = pk [16,16] — reproduced analytically (exact in fp32)
    float* out = (float*)d_out;                // [8192,128]

    const int n_patches = in_sizes[0] / NPIX;
    sift_desc_kernel<<<n_patches, NTHREADS>>>(x, gk, out);
}

// round 4
// speedup vs baseline: 2.8837x; 2.8837x over previous
#include <cuda_runtime.h>

#define PATCH 41
#define NPIX (PATCH * PATCH)
#define NBINS 128
#define NTHREADS 256

static __device__ __forceinline__ float block_reduce_sum(float v, float* red) {
    #pragma unroll
    for (int o = 16; o > 0; o >>= 1) v += __shfl_xor_sync(0xffffffffu, v, o);
    __syncthreads();
    if ((threadIdx.x & 31) == 0) red[threadIdx.x >> 5] = v;
    __syncthreads();
    float s = 0.f;
    #pragma unroll
    for (int w = 0; w < NTHREADS / 32; ++w) s += red[w];
    return s;
}

// fast atan2 matching atan2f(y, x) to ~2e-7 rad, range (-pi, pi]
static __device__ __forceinline__ float fast_atan2(float y, float x) {
    const float ax = fabsf(x), ay = fabsf(y);
    const float mx = fmaxf(ax, ay), mn = fminf(ax, ay);
    const float t = mn * __frcp_rn(fmaxf(mx, 1e-30f));
    const float s = t * t;
    // minimax poly for atan(t), t in [0,1]
    float r = -0.0117212f;
    r = fmaf(r, s,  0.05265332f);
    r = fmaf(r, s, -0.11643287f);
    r = fmaf(r, s,  0.19354346f);
    r = fmaf(r, s, -0.33262347f);
    r = fmaf(r, s,  0.99997726f);
    r = r * t;
    if (ay > ax) r = 1.57079632679f - r;
    if (x < 0.f) r = 3.14159265359f - r;
    return (y < 0.f) ? -r : r;
}

__global__ void __launch_bounds__(NTHREADS)
sift_desc_kernel(const float* __restrict__ x,
                 const float* __restrict__ gk,
                 float* __restrict__ out) {
    __shared__ float sx[NPIX];          // patch; later aliased as colsum[41*32]
    __shared__ float sm0[NPIX];
    __shared__ float sm1[NPIX];
    __shared__ unsigned char sb0[NPIX];
    __shared__ float red[NTHREADS / 32];

    const int p   = blockIdx.x;
    const int tid = threadIdx.x;
    const float* xp = x + (size_t)p * NPIX;

    for (int i = tid; i < NPIX; i += NTHREADS) sx[i] = xp[i];
    __syncthreads();

    const float TWO_PI = 6.28318530717958647692f;
    const float ANG_SCALE = 8.0f / TWO_PI;

    // ---- Phase 1: per-pixel gradient, magnitude, soft angular split ----
    for (int i = tid; i < NPIX; i += NTHREADS) {
        const int r = i / PATCH;
        const int c = i - r * PATCH;

        const float gxv = sx[r * PATCH + (c < PATCH - 1 ? c + 1 : c)]
                        - sx[r * PATCH + (c > 0 ? c - 1 : c)];
        const float gyv = sx[(r < PATCH - 1 ? r + 1 : r) * PATCH + c]
                        - sx[(r > 0 ? r - 1 : r) * PATCH + c];

        const float mag = sqrtf(fmaf(gxv, gxv, fmaf(gyv, gyv, 1e-10f))) * __ldg(&gk[i]);
        const float ori = fast_atan2(gyv, gxv + 1e-10f);

        const float f  = (ori + TWO_PI) * ANG_SCALE;   // in (4, 12]
        const float bf = floorf(f);
        const float w1 = f - bf;
        const int b0 = ((int)bf) & 7;

        sm0[i] = (1.0f - w1) * mag;
        sm1[i] = w1 * mag;
        sb0[i] = (unsigned char)b0;
    }
    __syncthreads();   // sx dead from here; reuse as colsum

    float* colsum = sx;   // [41][4][8] = 1312 floats

    // ---- Phase 2: horizontal pooling. thread owns (row r, x-bin ix) ----
    if (tid < PATCH * 4) {
        const int r  = tid >> 2;
        const int ix = tid & 3;
        const int x0 = 10 * ix - 4;
        const int cmin = max(0, x0);
        const int cmax = min(PATCH - 1, x0 + 15);

        float acc[8];
        #pragma unroll
        for (int k = 0; k < 8; ++k) acc[k] = 0.f;

        const int rowbase = r * PATCH;
        for (int c = cmin; c <= cmax; ++c) {
            const float dx = (float)(c - x0);
            const float wx = (8.0f - fabsf(dx - 7.5f)) * 0.125f;
            const int idx  = rowbase + c;
            const float wm0 = wx * sm0[idx];
            const float wm1 = wx * sm1[idx];
            const int b = sb0[idx];
            #pragma unroll
            for (int k = 0; k < 8; ++k) {
                float add = (b == k) ? wm0 : ((b == ((k + 7) & 7)) ? wm1 : 0.f);
                acc[k] += add;
            }
        }
        const int obase = (r << 5) + (ix << 3);
        #pragma unroll
        for (int k = 0; k < 8; ++k) colsum[obase + k] = acc[k];
    }
    __syncthreads();

    // ---- Phase 3: vertical pooling. thread = bin (a, iy, ix) ----
    float v = 0.f;
    if (tid < NBINS) {
        const int a  = tid >> 4;
        const int iy = (tid >> 2) & 3;
        const int ix = tid & 3;
        const int y0 = 10 * iy - 4;
        const int rmin = max(0, y0);
        const int rmax = min(PATCH - 1, y0 + 15);
        const int woff = (ix << 3) + a;
        float s = 0.f;
        for (int r = rmin; r <= rmax; ++r) {
            const float dy = (float)(r - y0);
            const float wy = (8.0f - fabsf(dy - 7.5f)) * 0.125f;
            s = fmaf(wy, colsum[(r << 5) + woff], s);
        }
        v = s;
    }

    // ---- normalization chain: L2 -> clip(0.2) -> L2 -> L1 -> sqrt ----
    const float s1 = block_reduce_sum(v * v, red);
    v = v / fmaxf(sqrtf(s1), 1e-12f);
    v = fminf(fmaxf(v, 0.0f), 0.2f);

    const float s2 = block_reduce_sum(v * v, red);
    v = v / fmaxf(sqrtf(s2), 1e-12f);

    const float s3 = block_reduce_sum(fabsf(v), red);
    v = v / fmaxf(s3, 1e-12f);

    if (tid < NBINS) out[(size_t)p * NBINS + tid] = sqrtf(v + 1e-10f);
}

extern "C" void kernel_launch(void* const* d_in, const int* in_sizes, int n_in,
                              void* d_out, int out_size) {
    const float* x  = (const float*)d_in[0];   // [8192,1,41,41]
    const float* gk = (const float*)d_in[1];   // [41,41]
    // d_in[2] = pk [16,16] — reproduced analytically (exact in fp32)
    float* out = (float*)d_out;                // [8192,128]

    const int n_patches = in_sizes[0] / NPIX;
    sift_desc_kernel<<<n_patches, NTHREADS>>>(x, gk, out);
}

// round 6
// speedup vs baseline: 3.5933x; 1.2461x over previous
#include <cuda_runtime.h>

#define PATCH 41
#define NPIX (PATCH * PATCH)
#define PADW 43
#define CSTRIDE 33              /* colsum row stride (pad 32 -> 33 vs banks) */
#define NBINS 128
#define NTHREADS 256

static __device__ __forceinline__ float block_reduce_sum(float v, float* red) {
    #pragma unroll
    for (int o = 16; o > 0; o >>= 1) v += __shfl_xor_sync(0xffffffffu, v, o);
    __syncthreads();
    if ((threadIdx.x & 31) == 0) red[threadIdx.x >> 5] = v;
    __syncthreads();
    float s = 0.f;
    #pragma unroll
    for (int w = 0; w < NTHREADS / 32; ++w) s += red[w];
    return s;
}

// atan2 scaled to bin units: returns atan2(y,x) * 4/pi, in (-4, 4]
static __device__ __forceinline__ float atan2_bins(float y, float x) {
    const float ax = fabsf(x), ay = fabsf(y);
    const float mx = fmaxf(ax, ay), mn = fminf(ax, ay);
    const float t = mn * __frcp_rn(fmaxf(mx, 1e-30f));
    const float s = t * t;
    // minimax poly for atan(t)*4/pi, t in [0,1]
    float r = -0.0149236f;
    r = fmaf(r, s,  0.0670411f);
    r = fmaf(r, s, -0.1482390f);
    r = fmaf(r, s,  0.2464268f);
    r = fmaf(r, s, -0.4235127f);
    r = fmaf(r, s,  1.2732107f);
    r = r * t;
    if (ay > ax) r = 2.0f - r;
    if (x < 0.f)  r = 4.0f - r;
    return (y < 0.f) ? -r : r;
}

__global__ void __launch_bounds__(NTHREADS)
sift_desc_kernel(const float* __restrict__ x,
                 const float* __restrict__ gk,
                 float* __restrict__ out) {
    // sxp: padded patch [43][43]; after phase 1 it is dead and the same
    // storage is reused as colsum [41][CSTRIDE] (1353 <= 1849 floats).
    __shared__ float salias[PADW * PADW];
    __shared__ float2 smm[NPIX];
    __shared__ unsigned char sb0[NPIX];
    __shared__ float red[NTHREADS / 32];

    const int p   = blockIdx.x;
    const int tid = threadIdx.x;
    const float* xp = x + (size_t)p * NPIX;

    float* sxp = salias;

    // ---- stage patch with replicated 1-px border ----
    for (int i = tid; i < NPIX; i += NTHREADS) {
        const int r = i / PATCH;
        const int c = i - r * PATCH;
        sxp[(r + 1) * PADW + (c + 1)] = xp[i];
    }
    if (tid < PATCH) {
        sxp[tid + 1]                        = xp[tid];                      // top
        sxp[(PATCH + 1) * PADW + tid + 1]   = xp[(PATCH - 1) * PATCH + tid];// bottom
        sxp[(tid + 1) * PADW]               = xp[tid * PATCH];              // left
        sxp[(tid + 1) * PADW + PATCH + 1]   = xp[tid * PATCH + PATCH - 1];  // right
    }
    __syncthreads();

    // ---- Phase 1: gradient, magnitude, soft angular split ----
    for (int i = tid; i < NPIX; i += NTHREADS) {
        const int r = i / PATCH;
        const int base = i + 2 * r + PADW + 1;   // (r+1)*43 + (c+1)

        const float gxv = sxp[base + 1]    - sxp[base - 1];
        const float gyv = sxp[base + PADW] - sxp[base - PADW];

        const float mag = sqrtf(fmaf(gxv, gxv, fmaf(gyv, gyv, 1e-10f))) * __ldg(&gk[i]);
        const float f   = atan2_bins(gyv, gxv + 1e-10f) + 8.0f;   // in (4, 12]

        const float bf = floorf(f);
        const float w1 = f - bf;
        const int b0 = ((int)bf) & 7;

        smm[i] = make_float2((1.0f - w1) * mag, w1 * mag);
        sb0[i] = (unsigned char)b0;
    }
    __syncthreads();   // sxp dead; reuse as colsum

    float* colsum = salias;   // [41][CSTRIDE], slots [r][ix*8 + a]

    // ---- Phase 2: horizontal pooling, scatter into thread-owned slice ----
    if (tid < PATCH * 4) {
        const int r  = tid >> 2;
        const int ix = tid & 3;
        const int x0 = 10 * ix - 4;
        const int obase   = r * CSTRIDE + (ix << 3);
        const int rowbase = r * PATCH;

        #pragma unroll
        for (int k = 0; k < 8; ++k) colsum[obase + k] = 0.f;

        #pragma unroll
        for (int j = 0; j < 16; ++j) {
            const float wxj = (8.0f - fabsf((float)j - 7.5f)) * 0.125f;  // compile-time
            const int c = x0 + j;
            const float w = ((unsigned)c < (unsigned)PATCH) ? wxj : 0.f;
            const int cc = (c < 0) ? 0 : ((c > PATCH - 1) ? PATCH - 1 : c);
            const int idx = rowbase + cc;
            const float2 mm = smm[idx];
            const int b = sb0[idx];
            colsum[obase + b]             += w * mm.x;
            colsum[obase + ((b + 1) & 7)] += w * mm.y;
        }
    }
    __syncthreads();

    // ---- Phase 3: vertical pooling. thread = bin (a, iy, ix) ----
    float v = 0.f;
    if (tid < NBINS) {
        const int a  = tid >> 4;
        const int iy = (tid >> 2) & 3;
        const int ix = tid & 3;
        const int y0 = 10 * iy - 4;
        const int rmin = max(0, y0);
        const int rmax = min(PATCH - 1, y0 + 15);
        const int woff = (ix << 3) + a;
        float s = 0.f;
        for (int r = rmin; r <= rmax; ++r) {
            const float wy = (8.0f - fabsf((float)(r - y0) - 7.5f)) * 0.125f;
            s = fmaf(wy, colsum[r * CSTRIDE + woff], s);
        }
        v = s;
    }

    // ---- normalization chain: L2 -> clip(0.2) -> L2 -> L1 -> sqrt ----
    const float s1 = block_reduce_sum(v * v, red);
    v = v / fmaxf(sqrtf(s1), 1e-12f);
    v = fminf(fmaxf(v, 0.0f), 0.2f);

    const float s2 = block_reduce_sum(v * v, red);
    v = v / fmaxf(sqrtf(s2), 1e-12f);

    const float s3 = block_reduce_sum(fabsf(v), red);
    v = v / fmaxf(s3, 1e-12f);

    if (tid < NBINS) out[(size_t)p * NBINS + tid] = sqrtf(v + 1e-10f);
}

extern "C" void kernel_launch(void* const* d_in, const int* in_sizes, int n_in,
                              void* d_out, int out_size) {
    const float* x  = (const float*)d_in[0];   // [8192,1,41,41]
    const float* gk = (const float*)d_in[1];   // [41,41]
    // d_in[2] = pk [16,16] — reproduced analytically (exact in fp32)
    float* out = (float*)d_out;                // [8192,128]

    const int n_patches = in_sizes[0] / NPIX;
    sift_desc_kernel<<<n_patches, NTHREADS>>>(x, gk, out);
}

// round 7
// speedup vs baseline: 3.8710x; 1.0773x over previous
#include <cuda_runtime.h>
#include <cuda_fp16.h>

#define PATCH 41
#define NPIX (PATCH * PATCH)
#define PADW 43
#define NCOL 164                 /* phase-2 threads: 41 rows x 4 x-bins */
#define CPITCH 168               /* colsum pitch: 164 padded */
#define NBINS 128
#define NTHREADS 256

static __device__ __forceinline__ float block_reduce_sum(float v, float* red) {
    #pragma unroll
    for (int o = 16; o > 0; o >>= 1) v += __shfl_xor_sync(0xffffffffu, v, o);
    __syncthreads();
    if ((threadIdx.x & 31) == 0) red[threadIdx.x >> 5] = v;
    __syncthreads();
    float s = 0.f;
    #pragma unroll
    for (int w = 0; w < NTHREADS / 32; ++w) s += red[w];
    return s;
}

// atan2 scaled to bin units: returns atan2(y,x) * 4/pi, in (-4, 4]
static __device__ __forceinline__ float atan2_bins(float y, float x) {
    const float ax = fabsf(x), ay = fabsf(y);
    const float mx = fmaxf(ax, ay), mn = fminf(ax, ay);
    const float t = mn * __frcp_rn(fmaxf(mx, 1e-30f));
    const float s = t * t;
    float r = -0.0149236f;
    r = fmaf(r, s,  0.0670411f);
    r = fmaf(r, s, -0.1482390f);
    r = fmaf(r, s,  0.2464268f);
    r = fmaf(r, s, -0.4235127f);
    r = fmaf(r, s,  1.2732107f);
    r = r * t;
    if (ay > ax) r = 2.0f - r;
    if (x < 0.f)  r = 4.0f - r;
    return (y < 0.f) ? -r : r;
}

__global__ void __launch_bounds__(NTHREADS)
sift_desc_kernel(const float* __restrict__ x,
                 const float* __restrict__ gk,
                 float* __restrict__ out) {
    // salias: padded patch [43][43] in phase 1; colsum [8][CPITCH] afterwards
    // (8*168 = 1344 <= 1849 floats).
    __shared__ float salias[PADW * PADW];
    __shared__ __half2 smm[NPIX];
    __shared__ unsigned char sb0[NPIX];
    __shared__ float red[NTHREADS / 32];

    const int p   = blockIdx.x;
    const int tid = threadIdx.x;
    const float* xp = x + (size_t)p * NPIX;

    float* sxp = salias;

    // ---- stage patch with replicated 1-px border ----
    for (int i = tid; i < NPIX; i += NTHREADS) {
        const int r = i / PATCH;
        const int c = i - r * PATCH;
        sxp[(r + 1) * PADW + (c + 1)] = xp[i];
    }
    if (tid < PATCH) {
        sxp[tid + 1]                        = xp[tid];                       // top
        sxp[(PATCH + 1) * PADW + tid + 1]   = xp[(PATCH - 1) * PATCH + tid]; // bottom
        sxp[(tid + 1) * PADW]               = xp[tid * PATCH];               // left
        sxp[(tid + 1) * PADW + PATCH + 1]   = xp[tid * PATCH + PATCH - 1];   // right
    }
    __syncthreads();

    // ---- Phase 1: gradient, magnitude, soft angular split ----
    for (int i = tid; i < NPIX; i += NTHREADS) {
        const int r = i / PATCH;
        const int base = i + 2 * r + PADW + 1;   // (r+1)*43 + (c+1)

        const float gxv = sxp[base + 1]    - sxp[base - 1];
        const float gyv = sxp[base + PADW] - sxp[base - PADW];

        const float mag = sqrtf(fmaf(gxv, gxv, fmaf(gyv, gyv, 1e-10f))) * __ldg(&gk[i]);
        const float f   = atan2_bins(gyv, gxv + 1e-10f) + 8.0f;   // in (4, 12]

        const float bf = floorf(f);
        const float w1 = f - bf;
        const int b0 = ((int)bf) & 7;

        smm[i] = __floats2half2_rn((1.0f - w1) * mag, w1 * mag);
        sb0[i] = (unsigned char)b0;
    }
    __syncthreads();   // sxp dead; reuse as colsum

    float* colsum = salias;   // [8][CPITCH]; address = bin*CPITCH + t

    // ---- Phase 2: horizontal pooling; thread t = (r, ix) owns column t.
    // Bank-conflict-free by construction: lanes have consecutive t, so any
    // per-lane bin b maps to 32 distinct banks at b*CPITCH + t.
    if (tid < NCOL) {
        const int t  = tid;
        const int r  = tid >> 2;
        const int ix = tid & 3;
        const int x0 = 10 * ix - 4;
        const int rowbase = r * PATCH;

        #pragma unroll
        for (int k = 0; k < 8; ++k) colsum[k * CPITCH + t] = 0.f;

        #pragma unroll
        for (int j = 0; j < 16; ++j) {
            const float wxj = (8.0f - fabsf((float)j - 7.5f)) * 0.125f;  // compile-time
            const int c = x0 + j;
            const float w = ((unsigned)c < (unsigned)PATCH) ? wxj : 0.f;
            const int cc = (c < 0) ? 0 : ((c > PATCH - 1) ? PATCH - 1 : c);
            const int idx = rowbase + cc;
            const float2 mm = __half22float2(smm[idx]);
            const int b = sb0[idx];
            colsum[b * CPITCH + t]             += w * mm.x;
            colsum[((b + 1) & 7) * CPITCH + t] += w * mm.y;
        }
    }
    __syncthreads();

    // ---- Phase 3: vertical pooling. thread = bin (a, iy, ix) ----
    float v = 0.f;
    if (tid < NBINS) {
        const int a  = tid >> 4;
        const int iy = (tid >> 2) & 3;
        const int ix = tid & 3;
        const int y0 = 10 * iy - 4;
        const int rmin = max(0, y0);
        const int rmax = min(PATCH - 1, y0 + 15);
        const int abase = a * CPITCH + ix;
        float s = 0.f;
        for (int r = rmin; r <= rmax; ++r) {
            const float wy = (8.0f - fabsf((float)(r - y0) - 7.5f)) * 0.125f;
            s = fmaf(wy, colsum[abase + (r << 2)], s);
        }
        v = s;
    }

    // ---- normalization chain: L2 -> clip(0.2) -> L2 -> L1 -> sqrt ----
    const float s1 = block_reduce_sum(v * v, red);
    v = v / fmaxf(sqrtf(s1), 1e-12f);
    v = fminf(fmaxf(v, 0.0f), 0.2f);

    const float s2 = block_reduce_sum(v * v, red);
    v = v / fmaxf(sqrtf(s2), 1e-12f);

    const float s3 = block_reduce_sum(fabsf(v), red);
    v = v / fmaxf(s3, 1e-12f);

    if (tid < NBINS) out[(size_t)p * NBINS + tid] = sqrtf(v + 1e-10f);
}

extern "C" void kernel_launch(void* const* d_in, const int* in_sizes, int n_in,
                              void* d_out, int out_size) {
    const float* x  = (const float*)d_in[0];   // [8192,1,41,41]
    const float* gk = (const float*)d_in[1];   // [41,41]
    // d_in[2] = pk [16,16] — reproduced analytically (exact in fp32)
    float* out = (float*)d_out;                // [8192,128]

    const int n_patches = in_sizes[0] / NPIX;
    sift_desc_kernel<<<n_patches, NTHREADS>>>(x, gk, out);
}

// round 8
// speedup vs baseline: 4.0545x; 1.0474x over previous
#include <cuda_runtime.h>
#include <cuda_fp16.h>

#define PATCH 41
#define NPIX (PATCH * PATCH)
#define PADW 43
#define NCOL 164                 /* phase-2 columns: 41 rows x 4 x-bins */
#define CPITCH 164               /* colsum pitch */
#define NBINS 128
#define NTHREADS 256

static __device__ __forceinline__ float block_reduce_sum(float v, float* red) {
    #pragma unroll
    for (int o = 16; o > 0; o >>= 1) v += __shfl_xor_sync(0xffffffffu, v, o);
    __syncthreads();
    if ((threadIdx.x & 31) == 0) red[threadIdx.x >> 5] = v;
    __syncthreads();
    float s = 0.f;
    #pragma unroll
    for (int w = 0; w < NTHREADS / 32; ++w) s += red[w];
    return s;
}

// atan2 scaled to bin units: returns atan2(y,x) * 4/pi, in (-4, 4]
static __device__ __forceinline__ float atan2_bins(float y, float x) {
    const float ax = fabsf(x), ay = fabsf(y);
    const float mx = fmaxf(ax, ay), mn = fminf(ax, ay);
    const float t = mn * __frcp_rn(fmaxf(mx, 1e-30f));
    const float s = t * t;
    float r = -0.0149236f;
    r = fmaf(r, s,  0.0670411f);
    r = fmaf(r, s, -0.1482390f);
    r = fmaf(r, s,  0.2464268f);
    r = fmaf(r, s, -0.4235127f);
    r = fmaf(r, s,  1.2732107f);
    r = r * t;
    if (ay > ax) r = 2.0f - r;
    if (x < 0.f)  r = 4.0f - r;
    return (y < 0.f) ? -r : r;
}

// Horizontal pooling body, compile-time trip bounds (all columns in-range).
template<int J0, int J1>
static __device__ __forceinline__ void hpool(const unsigned* __restrict__ smm,
                                             float* __restrict__ colsum,
                                             int rowbase, int x0, int u) {
    #pragma unroll
    for (int j = J0; j < J1; ++j) {
        const float wxj = (8.0f - fabsf((float)j - 7.5f)) * 0.125f;  // compile-time
        const unsigned v = smm[rowbase + x0 + j];
        const int b = v & 7;
        const float mag = __half2float(__ushort_as_half((unsigned short)(v >> 16)));
        const float w1q = (float)((v >> 3) & 0x1FFFu);
        const float t   = wxj * mag;
        const float wm1 = t * w1q * (1.0f / 8192.0f);
        const float wm0 = t - wm1;
        colsum[b * CPITCH + u]             += wm0;
        colsum[((b + 1) & 7) * CPITCH + u] += wm1;
    }
}

__global__ void __launch_bounds__(NTHREADS)
sift_desc_kernel(const float* __restrict__ x,
                 const float* __restrict__ gk,
                 float* __restrict__ out) {
    // salias: padded patch [43][43] in phase 1; colsum [8][CPITCH] afterwards
    // (8*164 = 1312 <= 1849 floats).
    __shared__ float salias[PADW * PADW];
    __shared__ unsigned smm[NPIX];       // mag:half<<16 | w1:13b<<3 | b0:3b
    __shared__ float red[NTHREADS / 32];

    const int p   = blockIdx.x;
    const int tid = threadIdx.x;
    const float* xp = x + (size_t)p * NPIX;

    float* sxp = salias;

    // ---- stage patch with replicated 1-px border ----
    for (int i = tid; i < NPIX; i += NTHREADS) {
        const int r = i / PATCH;
        const int c = i - r * PATCH;
        sxp[(r + 1) * PADW + (c + 1)] = xp[i];
    }
    if (tid < PATCH) {
        sxp[tid + 1]                        = xp[tid];                       // top
        sxp[(PATCH + 1) * PADW + tid + 1]   = xp[(PATCH - 1) * PATCH + tid]; // bottom
        sxp[(tid + 1) * PADW]               = xp[tid * PATCH];               // left
        sxp[(tid + 1) * PADW + PATCH + 1]   = xp[tid * PATCH + PATCH - 1];   // right
    }
    __syncthreads();

    // ---- Phase 1: gradient, magnitude, packed angular split ----
    for (int i = tid; i < NPIX; i += NTHREADS) {
        const int r = i / PATCH;
        const int base = i + 2 * r + PADW + 1;   // (r+1)*43 + (c+1)

        const float gxv = sxp[base + 1]    - sxp[base - 1];
        const float gyv = sxp[base + PADW] - sxp[base - PADW];

        const float mag = sqrtf(fmaf(gxv, gxv, fmaf(gyv, gyv, 1e-10f))) * __ldg(&gk[i]);
        const float f   = atan2_bins(gyv, gxv + 1e-10f) + 8.0f;   // in (4, 12]

        const float bf = floorf(f);
        const float w1 = f - bf;                 // [0, 1)
        const int b0 = ((int)bf) & 7;

        const unsigned hm  = (unsigned)__half_as_ushort(__float2half_rn(mag));
        const unsigned w1q = (unsigned)(w1 * 8192.0f);   // 0..8191 (trunc)
        smm[i] = (hm << 16) | (w1q << 3) | (unsigned)b0;
    }
    __syncthreads();   // sxp dead; reuse as colsum

    float* colsum = salias;   // [8][CPITCH]; address = bin*CPITCH + u

    // zero colsum with all threads
    for (int k = tid; k < 8 * CPITCH; k += NTHREADS) colsum[k] = 0.f;
    __syncthreads();

    // ---- Phase 2: horizontal pooling; column u = ix*41 + r ----
    if (tid < 128) {
        // ix-pure warps: warp w handles ix=w, rows 0..31
        const int ix = tid >> 5;
        const int r  = tid & 31;
        const int u  = ix * PATCH + r;
        const int rowbase = r * PATCH;
        const int x0 = 10 * ix - 4;
        switch (ix) {                       // warp-uniform branch
            case 0: hpool<4, 16>(smm, colsum, rowbase, x0, u); break;
            case 1: hpool<0, 16>(smm, colsum, rowbase, x0, u); break;
            case 2: hpool<0, 16>(smm, colsum, rowbase, x0, u); break;
            default: hpool<0, 15>(smm, colsum, rowbase, x0, u); break;
        }
    } else if (tid < 128 + 36) {
        // tail rows 32..40, mixed ix: generic clamped loop
        const int k  = tid - 128;
        const int r  = 32 + (k >> 2);
        const int ix = k & 3;
        const int u  = ix * PATCH + r;
        const int rowbase = r * PATCH;
        const int x0 = 10 * ix - 4;
        #pragma unroll
        for (int j = 0; j < 16; ++j) {
            const float wxj = (8.0f - fabsf((float)j - 7.5f)) * 0.125f;
            const int c = x0 + j;
            const float w = ((unsigned)c < (unsigned)PATCH) ? wxj : 0.f;
            const int cc = (c < 0) ? 0 : ((c > PATCH - 1) ? PATCH - 1 : c);
            const unsigned v = smm[rowbase + cc];
            const int b = v & 7;
            const float mag = __half2float(__ushort_as_half((unsigned short)(v >> 16)));
            const float w1q = (float)((v >> 3) & 0x1FFFu);
            const float t   = w * mag;
            const float wm1 = t * w1q * (1.0f / 8192.0f);
            const float wm0 = t - wm1;
            colsum[b * CPITCH + u]             += wm0;
            colsum[((b + 1) & 7) * CPITCH + u] += wm1;
        }
    }
    __syncthreads();

    // ---- Phase 3: vertical pooling. thread = bin (a, iy, ix) ----
    float v = 0.f;
    if (tid < NBINS) {
        const int a  = tid >> 4;
        const int iy = (tid >> 2) & 3;
        const int ix = tid & 3;
        const int y0 = 10 * iy - 4;
        const int rmin = max(0, y0);
        const int rmax = min(PATCH - 1, y0 + 15);
        const int abase = a * CPITCH + ix * PATCH;
        float s = 0.f;
        for (int r = rmin; r <= rmax; ++r) {
            const float wy = (8.0f - fabsf((float)(r - y0) - 7.5f)) * 0.125f;
            s = fmaf(wy, colsum[abase + r], s);
        }
        v = s;
    }

    // ---- normalization chain: L2 -> clip(0.2) -> L2 -> L1 -> sqrt ----
    const float s1 = block_reduce_sum(v * v, red);
    v = v / fmaxf(sqrtf(s1), 1e-12f);
    v = fminf(fmaxf(v, 0.0f), 0.2f);

    const float s2 = block_reduce_sum(v * v, red);
    v = v / fmaxf(sqrtf(s2), 1e-12f);

    const float s3 = block_reduce_sum(fabsf(v), red);
    v = v / fmaxf(s3, 1e-12f);

    if (tid < NBINS) out[(size_t)p * NBINS + tid] = sqrtf(v + 1e-10f);
}

extern "C" void kernel_launch(void* const* d_in, const int* in_sizes, int n_in,
                              void* d_out, int out_size) {
    const float* x  = (const float*)d_in[0];   // [8192,1,41,41]
    const float* gk = (const float*)d_in[1];   // [41,41]
    // d_in[2] = pk [16,16] — reproduced analytically (exact in fp32)
    float* out = (float*)d_out;                // [8192,128]

    const int n_patches = in_sizes[0] / NPIX;
    sift_desc_kernel<<<n_patches, NTHREADS>>>(x, gk, out);
}

// round 10
// speedup vs baseline: 4.2451x; 1.0470x over previous
#include <cuda_runtime.h>
#include <cuda_fp16.h>

#define PATCH 41
#define NPIX (PATCH * PATCH)
#define PADW 43
#define CPITCH 164               /* colsum pitch (9 rows: 8 bins + mirror of bin0) */
#define NBINS 128
#define NTHREADS 256

static __device__ __forceinline__ float block_reduce_sum(float v, float* red) {
    #pragma unroll
    for (int o = 16; o > 0; o >>= 1) v += __shfl_xor_sync(0xffffffffu, v, o);
    __syncthreads();
    if ((threadIdx.x & 31) == 0) red[threadIdx.x >> 5] = v;
    __syncthreads();
    float s = 0.f;
    #pragma unroll
    for (int w = 0; w < NTHREADS / 32; ++w) s += red[w];
    return s;
}

// atan2 scaled to bin units: returns atan2(y,x) * 4/pi, in (-4, 4]
static __device__ __forceinline__ float atan2_bins(float y, float x) {
    const float ax = fabsf(x), ay = fabsf(y);
    const float mx = fmaxf(ax, ay), mn = fminf(ax, ay);
    const float t = mn * __frcp_rn(fmaxf(mx, 1e-30f));
    const float s = t * t;
    float r = -0.0149236f;
    r = fmaf(r, s,  0.0670411f);
    r = fmaf(r, s, -0.1482390f);
    r = fmaf(r, s,  0.2464268f);
    r = fmaf(r, s, -0.4235127f);
    r = fmaf(r, s,  1.2732107f);
    r = r * t;
    if (ay > ax) r = 2.0f - r;
    if (x < 0.f)  r = 4.0f - r;
    return (y < 0.f) ? -r : r;
}

// One horizontal-pooling contribution. smm word: mag(half)<<16 | fq16
// where fq16 bits[15:13] = bin, bits[12:0] = 8192*w1.
// Second scatter target is ALWAYS addr+CPITCH (row 8 mirrors bin 0).
static __device__ __forceinline__ void hstep(unsigned v, float wxj, float wxj_s,
                                             float* __restrict__ colsum, int u) {
    const int b = (v >> 13) & 7;
    const float mag = __half2float(__ushort_as_half((unsigned short)(v >> 16)));
    const float w1f = (float)(v & 0x1FFFu);
    const float wm1 = wxj_s * (mag * w1f);
    const float wm0 = fmaf(wxj, mag, -wm1);
    float* a0 = &colsum[b * CPITCH + u];
    a0[0]      += wm0;
    a0[CPITCH] += wm1;
}

// Horizontal pooling body, compile-time trip bounds (all columns in-range).
template<int J0, int J1>
static __device__ __forceinline__ void hpool(const unsigned* __restrict__ smm,
                                             float* __restrict__ colsum,
                                             int rowbase, int x0, int u) {
    #pragma unroll
    for (int j = J0; j < J1; ++j) {
        const float wxj   = (8.0f - fabsf((float)j - 7.5f)) * 0.125f;   // compile-time
        const float wxj_s = wxj * (1.0f / 8192.0f);                     // compile-time
        hstep(smm[rowbase + x0 + j], wxj, wxj_s, colsum, u);
    }
}

__global__ void __launch_bounds__(NTHREADS)
sift_desc_kernel(const float* __restrict__ x,
                 const float* __restrict__ gk,
                 float* __restrict__ out) {
    // salias: padded patch [43][43] (1849 fl) in phase 1; colsum [9][CPITCH]
    // (1476 fl) afterwards.
    __shared__ float salias[PADW * PADW];
    __shared__ unsigned smm[NPIX];       // mag:half<<16 | fq:16
    __shared__ float red[NTHREADS / 32];

    const int p   = blockIdx.x;
    const int tid = threadIdx.x;
    const float* xp = x + (size_t)p * NPIX;

    float* sxp = salias;

    // ---- stage patch with replicated 1-px border ----
    for (int i = tid; i < NPIX; i += NTHREADS) {
        const int r = i / PATCH;
        const int c = i - r * PATCH;
        sxp[(r + 1) * PADW + (c + 1)] = xp[i];
    }
    if (tid < PATCH) {
        sxp[tid + 1]                        = xp[tid];                       // top
        sxp[(PATCH + 1) * PADW + tid + 1]   = xp[(PATCH - 1) * PATCH + tid]; // bottom
        sxp[(tid + 1) * PADW]               = xp[tid * PATCH];               // left
        sxp[(tid + 1) * PADW + PATCH + 1]   = xp[tid * PATCH + PATCH - 1];   // right
    }
    __syncthreads();

    // ---- Phase 1: gradient, magnitude, packed angular split ----
    for (int i = tid; i < NPIX; i += NTHREADS) {
        const int r = i / PATCH;
        const int base = i + 2 * r + PADW + 1;   // (r+1)*43 + (c+1)

        const float gxv = sxp[base + 1]    - sxp[base - 1];
        const float gyv = sxp[base + PADW] - sxp[base - PADW];

        const float mag = sqrtf(fmaf(gxv, gxv, fmaf(gyv, gyv, 1e-10f))) * __ldg(&gk[i]);
        const float f   = atan2_bins(gyv, gxv + 1e-10f) + 8.0f;   // in (4, 12]

        // fq low 16 bits: [15:13] = bin (mod 8), [12:0] = w1 * 8192 (exact split:
        // f*8192 is a pure power-of-2 scale, so trunc == floor+trunc)
        const int fq = (int)(f * 8192.0f);
        const unsigned hm = (unsigned)__half_as_ushort(__float2half_rn(mag));
        smm[i] = (hm << 16) | ((unsigned)fq & 0xFFFFu);
    }
    __syncthreads();   // sxp dead; reuse as colsum

    float* colsum = salias;   // [9][CPITCH]; row 8 mirrors bin 0

    for (int k = tid; k < 9 * CPITCH; k += NTHREADS) colsum[k] = 0.f;
    __syncthreads();

    // ---- Phase 2: horizontal pooling; column u = ix*41 + r ----
    if (tid < 128) {
        // ix-pure warps: warp w handles ix=w, rows 0..31
        const int ix = tid >> 5;
        const int r  = tid & 31;
        const int u  = ix * PATCH + r;
        const int rowbase = r * PATCH;
        const int x0 = 10 * ix - 4;
        switch (ix) {                       // warp-uniform branch
            case 0: hpool<4, 16>(smm, colsum, rowbase, x0, u); break;
            case 1: hpool<0, 16>(smm, colsum, rowbase, x0, u); break;
            case 2: hpool<0, 16>(smm, colsum, rowbase, x0, u); break;
            default: hpool<0, 15>(smm, colsum, rowbase, x0, u); break;
        }
    } else if (tid < 128 + 36) {
        // tail rows 32..40, mixed ix: generic clamped loop
        const int k  = tid - 128;
        const int r  = 32 + (k >> 2);
        const int ix = k & 3;
        const int u  = ix * PATCH + r;
        const int rowbase = r * PATCH;
        const int x0 = 10 * ix - 4;
        #pragma unroll
        for (int j = 0; j < 16; ++j) {
            const float wxj0 = (8.0f - fabsf((float)j - 7.5f)) * 0.125f;
            const int c = x0 + j;
            const float w = ((unsigned)c < (unsigned)PATCH) ? wxj0 : 0.f;
            const int cc = (c < 0) ? 0 : ((c > PATCH - 1) ? PATCH - 1 : c);
            hstep(smm[rowbase + cc], w, w * (1.0f / 8192.0f), colsum, u);
        }
    }
    __syncthreads();

    // ---- Phase 3: vertical pooling. thread = bin (a, iy, ix) ----
    float v = 0.f;
    if (tid < NBINS) {
        const int a  = tid >> 4;
        const int iy = (tid >> 2) & 3;
        const int ix = tid & 3;
        const int y0 = 10 * iy - 4;
        const int rmin = max(0, y0);
        const int rmax = min(PATCH - 1, y0 + 15);
        const int abase = a * CPITCH + ix * PATCH;
        const int mbase = 8 * CPITCH + ix * PATCH;   // mirror row for bin 0
        float s = 0.f;
        for (int r = rmin; r <= rmax; ++r) {
            const float wy = (8.0f - fabsf((float)(r - y0) - 7.5f)) * 0.125f;
            float val = colsum[abase + r];
            if (a == 0) val += colsum[mbase + r];
            s = fmaf(wy, val, s);
        }
        v = s;
    }

    // ---- normalization chain: L2 -> clip(0.2) -> L2 -> L1 -> sqrt ----
    const float s1 = block_reduce_sum(v * v, red);
    v = v * rsqrtf(fmaxf(s1, 1e-24f));
    v = fminf(fmaxf(v, 0.0f), 0.2f);

    const float s2 = block_reduce_sum(v * v, red);
    v = v * rsqrtf(fmaxf(s2, 1e-24f));

    const float s3 = block_reduce_sum(fabsf(v), red);
    v = v * __frcp_rn(fmaxf(s3, 1e-12f));

    if (tid < NBINS) out[(size_t)p * NBINS + tid] = sqrtf(v + 1e-10f);
}

extern "C" void kernel_launch(void* const* d_in, const int* in_sizes, int n_in,
                              void* d_out, int out_size) {
    const float* x  = (const float*)d_in[0];   // [8192,1,41,41]
    const float* gk = (const float*)d_in[1];   // [41,41]
    // d_in[2] = pk [16,16] — reproduced analytically (exact in fp32)
    float* out = (float*)d_out;                // [8192,128]

    const int n_patches = in_sizes[0] / NPIX;
    sift_desc_kernel<<<n_patches, NTHREADS>>>(x, gk, out);
}